// round 5
// baseline (speedup 1.0000x reference)
#include <cuda_runtime.h>
#include <cuda_fp16.h>

#define N_NODES 50000
#define N_EDGES 1600000
#define NCLS    48
#define NH2     24            // active half2 per row
#define ROWP    32            // padded half2 per row (128B rows)
#define NSTEP   10
#define SCAN_B  1024
#define CHUNK   49            // ceil(50000/1024)

// ---------------- device scratch (static, no runtime allocation) -------------
__device__ float   g_deg[N_NODES];
__device__ int     g_cnt[N_NODES];
__device__ int     g_off[N_NODES + 1];
__device__ int     g_cur[N_NODES];
__device__ short   g_cls[N_EDGES];                   // target[src] per original edge
__device__ __align__(16) int2 g_edge[N_EDGES];       // (src, weight packed half2(w,w))
__device__ __align__(16) int  g_e1[N_EDGES];         // (cls<<16 | w_half_bits), CSR order
__device__ __half2 g_hh[2][(size_t)N_NODES * ROWP];  // fp16 feature buffers, 128B rows

static __device__ __forceinline__ __half2 bits2h2(int b) {
    __half2 h; *reinterpret_cast<int*>(&h) = b; return h;
}

// ---------------- preprocessing ------------------------------------------------
// degree accumulation + in-degree counting + src-class fetch
__global__ void deg_kernel(const int* __restrict__ row, const int* __restrict__ col,
                           const float* __restrict__ attr, const int* __restrict__ target) {
    int e = blockIdx.x * blockDim.x + threadIdx.x;
    if (e < N_EDGES) {
        int r = row[e];
        atomicAdd(&g_deg[r], attr[e]);
        atomicAdd(&g_cnt[col[e]], 1);
        g_cls[e] = (short)target[r];       // 200KB table: mostly L1/L2 hits
    }
}

// single-block exclusive scan of g_cnt -> g_off / g_cur (3-phase)
__global__ void scan_kernel() {
    __shared__ int sh[SCAN_B];
    int tid = threadIdx.x;
    int base = tid * CHUNK;

    int sum = 0;
    #pragma unroll 4
    for (int k = 0; k < CHUNK; k++) {
        int i = base + k;
        if (i < N_NODES) sum += g_cnt[i];
    }
    sh[tid] = sum;
    __syncthreads();
    for (int d = 1; d < SCAN_B; d <<= 1) {
        int t = (tid >= d) ? sh[tid - d] : 0;
        __syncthreads();
        sh[tid] += t;
        __syncthreads();
    }
    int run = sh[tid] - sum;
    #pragma unroll 4
    for (int k = 0; k < CHUNK; k++) {
        int i = base + k;
        if (i < N_NODES) {
            g_off[i] = run;
            g_cur[i] = run;
            run += g_cnt[i];
        }
    }
    if (tid == 0) g_off[N_NODES] = N_EDGES;
}

// bucket edges by destination; build both metadata arrays
__global__ void fill_kernel(const int* __restrict__ row, const int* __restrict__ col,
                            const float* __restrict__ attr) {
    int e = blockIdx.x * blockDim.x + threadIdx.x;
    if (e < N_EDGES) {
        int r = row[e];
        int c = col[e];
        float w = attr[e] / fmaxf(g_deg[r], 1e-12f);
        __half wh = __float2half_rn(w);
        unsigned short wb = __half_as_ushort(wh);
        __half2 wh2 = __halves2half2(wh, wh);
        int p = atomicAdd(&g_cur[c], 1);
        g_edge[p] = make_int2(r, *reinterpret_cast<int*>(&wh2));
        g_e1[p]   = ((int)g_cls[e] << 16) | (int)wb;
    }
}

// ---------------- step 0: one-hot propagation, no feature reads ----------------
// h1[n][c] = sum over in-edges with target[src]==c of w. Pure meta stream + ALU.
__global__ void __launch_bounds__(256)
step1_kernel(const float* __restrict__ Wm, float* __restrict__ out) {
    int gwarp = (blockIdx.x * blockDim.x + threadIdx.x) >> 5;
    int lane  = threadIdx.x & 31;
    if (gwarp >= N_NODES) return;

    __half2* __restrict__ hout = g_hh[1];

    int beg = g_off[gwarp];
    int end = g_off[gwarp + 1];
    bool act = (lane < NH2);

    float accx = 0.f, accy = 0.f;
    int c0 = 2 * lane, c1 = 2 * lane + 1;

    int j = beg;
    // peel to 16B alignment
    for (; j < end && (j & 3); j++) {
        int v = __ldcs(&g_e1[j]);
        int c = v >> 16;
        float w = __half2float(__ushort_as_half((unsigned short)(v & 0xffff)));
        accx += (c == c0) ? w : 0.f;
        accy += (c == c1) ? w : 0.f;
    }
    for (; j + 4 <= end; j += 4) {
        int4 m = __ldcs(reinterpret_cast<const int4*>(g_e1 + j));
        #pragma unroll
        for (int k = 0; k < 4; k++) {
            int v = (k == 0) ? m.x : (k == 1) ? m.y : (k == 2) ? m.z : m.w;
            int c = v >> 16;
            float w = __half2float(__ushort_as_half((unsigned short)(v & 0xffff)));
            accx += (c == c0) ? w : 0.f;
            accy += (c == c1) ? w : 0.f;
        }
    }
    for (; j < end; j++) {
        int v = __ldcs(&g_e1[j]);
        int c = v >> 16;
        float w = __half2float(__ushort_as_half((unsigned short)(v & 0xffff)));
        accx += (c == c0) ? w : 0.f;
        accy += (c == c1) ? w : 0.f;
    }

    if (act) {
        hout[(size_t)gwarp * ROWP + lane] = __floats2half2_rn(accx, accy);
        float2 o;
        o.x = accx * Wm[c0 * NSTEP];     // s = 0
        o.y = accy * Wm[c1 * NSTEP];
        float2* op = (float2*)(out + (size_t)gwarp * NCLS) + lane;
        *op = o;                          // first step: overwrite poisoned out
    }
}

// ---------------- steps 1..9: one warp per destination node -------------------
// lanes 0..23 own classes (2l, 2l+1); HFMA2 accumulate, promote to fp32 per 8
__global__ void __launch_bounds__(256)
gather_kernel(const float* __restrict__ Wm, float* __restrict__ out, int s) {
    int gwarp = (blockIdx.x * blockDim.x + threadIdx.x) >> 5;
    int lane  = threadIdx.x & 31;
    if (gwarp >= N_NODES) return;

    const __half2* __restrict__ hin  = g_hh[s & 1] + lane;   // lane-offset base
    __half2*       __restrict__ hout = g_hh[(s & 1) ^ 1];

    int beg = g_off[gwarp];
    int end = g_off[gwarp + 1];
    bool act = (lane < NH2);

    float accx = 0.f, accy = 0.f;
    __half2 hacc = __floats2half2_rn(0.f, 0.f);   // peel + remainder accumulator

    int j = beg;
    // peel one edge if beg is odd (align int4 metadata loads)
    if ((j & 1) && j < end) {
        int2 e = g_edge[j];
        if (act) {
            __half2 x = hin[(unsigned)e.x << 5];
            hacc = __hfma2(bits2h2(e.y), x, hacc);
        }
        j++;
    }

    for (; j + 8 <= end; j += 8) {
        int4 m0 = __ldcs(reinterpret_cast<const int4*>(g_edge + j));
        int4 m1 = __ldcs(reinterpret_cast<const int4*>(g_edge + j + 2));
        int4 m2 = __ldcs(reinterpret_cast<const int4*>(g_edge + j + 4));
        int4 m3 = __ldcs(reinterpret_cast<const int4*>(g_edge + j + 6));
        if (act) {
            __half2 x0 = hin[(unsigned)m0.x << 5];
            __half2 x1 = hin[(unsigned)m0.z << 5];
            __half2 x2 = hin[(unsigned)m1.x << 5];
            __half2 x3 = hin[(unsigned)m1.z << 5];
            __half2 x4 = hin[(unsigned)m2.x << 5];
            __half2 x5 = hin[(unsigned)m2.z << 5];
            __half2 x6 = hin[(unsigned)m3.x << 5];
            __half2 x7 = hin[(unsigned)m3.z << 5];
            __half2 p0 = __hmul2(bits2h2(m0.y), x0);
            __half2 p1 = __hmul2(bits2h2(m0.w), x1);
            p0 = __hfma2(bits2h2(m1.y), x2, p0);
            p1 = __hfma2(bits2h2(m1.w), x3, p1);
            p0 = __hfma2(bits2h2(m2.y), x4, p0);
            p1 = __hfma2(bits2h2(m2.w), x5, p1);
            p0 = __hfma2(bits2h2(m3.y), x6, p0);
            p1 = __hfma2(bits2h2(m3.w), x7, p1);
            float2 f = __half22float2(__hadd2(p0, p1));
            accx += f.x;
            accy += f.y;
        }
    }
    for (; j < end; j++) {
        int2 e = g_edge[j];
        if (act) {
            __half2 x = hin[(unsigned)e.x << 5];
            hacc = __hfma2(bits2h2(e.y), x, hacc);
        }
    }

    if (act) {
        float2 fr = __half22float2(hacc);
        accx += fr.x;
        accy += fr.y;

        hout[(size_t)gwarp * ROWP + lane] = __floats2half2_rn(accx, accy);

        float2 o;
        o.x = accx * Wm[(2 * lane) * NSTEP + s];
        o.y = accy * Wm[(2 * lane + 1) * NSTEP + s];
        float2* op = (float2*)(out + (size_t)gwarp * NCLS) + lane;
        float2 p = *op; o.x += p.x; o.y += p.y;
        *op = o;
    }
}

// ---------------- launch ------------------------------------------------------
extern "C" void kernel_launch(void* const* d_in, const int* in_sizes, int n_in,
                              void* d_out, int out_size) {
    const int*   ei     = (const int*)d_in[0];     // [2, E]
    const int*   row    = ei;
    const int*   col    = ei + N_EDGES;
    const float* attr   = (const float*)d_in[1];   // [E]
    const int*   target = (const int*)d_in[2];     // [N]
    const float* Wm     = (const float*)d_in[3];   // [C, S]
    float*       out    = (float*)d_out;           // [N, C]

    void* p_deg = nullptr; void* p_cnt = nullptr;
    cudaGetSymbolAddress(&p_deg, g_deg);
    cudaGetSymbolAddress(&p_cnt, g_cnt);
    cudaMemsetAsync(p_deg, 0, N_NODES * sizeof(float));
    cudaMemsetAsync(p_cnt, 0, N_NODES * sizeof(int));

    const int TB = 256;
    int nblk_edges = (N_EDGES + TB - 1) / TB;
    int nblk_warp  = (N_NODES + 7) / 8;    // 8 warps/block, 1 node/warp

    deg_kernel<<<nblk_edges, TB>>>(row, col, attr, target);   // launch 1
    scan_kernel<<<1, SCAN_B>>>();                             // launch 2
    fill_kernel<<<nblk_edges, TB>>>(row, col, attr);          // launch 3

    step1_kernel<<<nblk_warp, TB>>>(Wm, out);                 // launch 4 (s=0)
    for (int s = 1; s < NSTEP; s++) {
        gather_kernel<<<nblk_warp, TB>>>(Wm, out, s);         // launches 5..13
    }
}